// round 5
// baseline (speedup 1.0000x reference)
#include <cuda_runtime.h>
#include <cuda_bf16.h>
#include <math.h>

// ============================================================================
// Encoder_multi via 3x-bf16 split MMA (m16n8k16), fragment-permuted smem.
//   C[8192,3072] = A[8192,K] · W_sel[3072,K]^T, K=512 (L0) / 1024 (L1)
//   n packing: n = h*6 + dir*3 + gate(i,g,o) -> fused LSTM-cell epilogue.
//   Split: v = hi + lo (bf16); C = hh + hl + lh  (drop ll: ~2^-18 rel).
// Block: BM=128, BN=48 (8 h), KT=32, 256 thr, 8 warps (4m x 2n), 2 CTAs/SM.
// ============================================================================

#define M_TOTAL 8192
#define OUT_C   32768
#define OUT_ENC 65536

// word (b32) offsets inside one k-tile buffer
#define A_HI 0            // [ks2][slot32][mt8] uint4  (2048 words)
#define A_LO 2048
#define B_HI 4096         // [ks2][slot32][pos8] uint2 (1024 words)
#define B_LO 5120
#define BUF  6144         // words per buffer
#define SMEM_BYTES (2 * BUF * 4)   // 49152 B

__device__ float g_inp1[M_TOTAL * 1024];

__device__ __forceinline__ float sigmoidf_(float x) { return 1.0f / (1.0f + expf(-x)); }

__device__ __forceinline__ void mma16(float c[4], const uint4& a, const uint2& b) {
    asm volatile(
        "mma.sync.aligned.m16n8k16.row.col.f32.bf16.bf16.f32 "
        "{%0,%1,%2,%3}, {%4,%5,%6,%7}, {%8,%9}, {%0,%1,%2,%3};"
        : "+f"(c[0]), "+f"(c[1]), "+f"(c[2]), "+f"(c[3])
        : "r"(a.x), "r"(a.y), "r"(a.z), "r"(a.w), "r"(b.x), "r"(b.y));
}

// split one fp32 pair (k even, k odd) into packed bf16x2 hi + lo
__device__ __forceinline__ void split2(float x, float y, unsigned& hi, unsigned& lo) {
    __nv_bfloat162 h = __float22bfloat162_rn(make_float2(x, y));
    float lx = x - __bfloat162float(h.x);
    float ly = y - __bfloat162float(h.y);
    __nv_bfloat162 l = __float22bfloat162_rn(make_float2(lx, ly));
    hi = *(unsigned*)&h;
    lo = *(unsigned*)&l;
}

template<int LAYER, int K>
__global__ __launch_bounds__(256, 2)
void lstm_bf16(const int* __restrict__ x, const float* __restrict__ emb,
               const float* __restrict__ W, const float* __restrict__ b_ih,
               const float* __restrict__ b_hh, float* __restrict__ out)
{
    extern __shared__ float sm[];
    __shared__ int   sx[128];
    __shared__ float sBias[48];

    const int tid = threadIdx.x;
    const int m0  = blockIdx.x * 128;
    const int h0  = blockIdx.y * 8;

    if (LAYER == 0 && tid < 128) sx[tid] = x[m0 + tid];
    if (tid < 48) {
        int hl = tid / 6, rem = tid - hl * 6;
        int dir = (rem >= 3) ? 1 : 0, g = rem - dir * 3;
        int goff = (g == 0) ? 0 : ((g == 1) ? 1024 : 1536);
        int wrow = dir * 2048 + goff + h0 + hl;
        sBias[tid] = b_ih[wrow] + b_hh[wrow];
    }
    __syncthreads();

    // ---- producer setup ----
    // A: thread -> row r = tid&127, k-half ksp = tid>>7; 4 float4 per k-tile.
    const int r    = tid & 127;
    const int ksp  = tid >> 7;
    const int a_gq = r & 7, a_hm = (r >> 3) & 1, a_mtg = r >> 4;
    const float* arow = (LAYER == 0) ? (emb + (size_t)sx[r] * 512)
                                     : (g_inp1 + (size_t)(m0 + r) * 1024);
    // B: threads 0..191 -> row n = tid>>2, koff = (tid&3)*8; 2 float4.
    const int  bn   = tid >> 2;
    const int  koff = (tid & 3) * 8;
    const float* brow;
    int b_gq = 0, b_ntg = 0;
    if (tid < 192) {
        int hl = bn / 6, rem = bn - hl * 6;
        int dir = (rem >= 3) ? 1 : 0, g = rem - dir * 3;
        int goff = (g == 0) ? 0 : ((g == 1) ? 1024 : 1536);
        brow  = W + (size_t)(dir * 2048 + goff + h0 + hl) * K;
        b_gq  = bn & 7;
        b_ntg = bn >> 3;
    } else brow = W;

    // ---- consumer setup ----
    const int warp = tid >> 5, lane = tid & 31;
    const int wm = warp >> 1, wn = warp & 1;
    const int gq = lane >> 2, tg = lane & 3;

    float acc[2][3][4];
    #pragma unroll
    for (int mt = 0; mt < 2; ++mt)
        #pragma unroll
        for (int nt = 0; nt < 3; ++nt)
            #pragma unroll
            for (int j = 0; j < 4; ++j) acc[mt][nt][j] = 0.0f;

    constexpr int NITER = K / 32;
    float4 ra[4], rb[2];

    auto loadT = [&](int it) {
        const int kb = it * 32;
        #pragma unroll
        for (int p = 0; p < 4; ++p)
            ra[p] = *(const float4*)(arow + kb + ksp * 16 + p * 4);
        if (tid < 192) {
            rb[0] = *(const float4*)(brow + kb + koff);
            rb[1] = *(const float4*)(brow + kb + koff + 4);
        }
    };

    auto storeT = [&](unsigned* buf) {
        // A: each float4 (r, k..k+3) -> two bf16x2 frags (hi & lo planes)
        #pragma unroll
        for (int p = 0; p < 4; ++p) {
            const int hk  = p >> 1;
            const int tg0 = (p & 1) * 2;
            const int reg = a_hm + 2 * hk;
            unsigned h0_, l0_, h1_, l1_;
            split2(ra[p].x, ra[p].y, h0_, l0_);
            split2(ra[p].z, ra[p].w, h1_, l1_);
            int slot0 = a_gq * 4 + tg0;
            int slot1 = slot0 + 1;
            int w0 = ((ksp * 32 + slot0) * 8 + (a_mtg ^ (slot0 & 7))) * 4 + reg;
            int w1 = ((ksp * 32 + slot1) * 8 + (a_mtg ^ (slot1 & 7))) * 4 + reg;
            buf[A_HI + w0] = h0_;  buf[A_LO + w0] = l0_;
            buf[A_HI + w1] = h1_;  buf[A_LO + w1] = l1_;
        }
        // B
        if (tid < 192) {
            #pragma unroll
            for (int q = 0; q < 2; ++q) {
                const int k   = koff + q * 4;
                const int ksb = k >> 4, ki = k & 15;
                const int hk  = ki >> 3;
                const int tg0 = (ki & 7) >> 1;
                unsigned h0_, l0_, h1_, l1_;
                split2(rb[q].x, rb[q].y, h0_, l0_);
                split2(rb[q].z, rb[q].w, h1_, l1_);
                int slot0 = b_gq * 4 + tg0;
                int slot1 = slot0 + 1;
                int w0 = ((ksb * 32 + slot0) * 8 + (b_ntg ^ ((slot0 >> 1) & 7))) * 2 + hk;
                int w1 = ((ksb * 32 + slot1) * 8 + (b_ntg ^ ((slot1 >> 1) & 7))) * 2 + hk;
                buf[B_HI + w0] = h0_;  buf[B_LO + w0] = l0_;
                buf[B_HI + w1] = h1_;  buf[B_LO + w1] = l1_;
            }
        }
    };

    loadT(0);
    storeT((unsigned*)sm);
    __syncthreads();

    for (int it = 0; it < NITER; ++it) {
        if (it + 1 < NITER) loadT(it + 1);

        const unsigned* buf = (const unsigned*)sm + (it & 1) * BUF;
        #pragma unroll
        for (int ks = 0; ks < 2; ++ks) {
            uint4 ah[2], al[2];
            #pragma unroll
            for (int mt = 0; mt < 2; ++mt) {
                int i4 = (ks * 32 + lane) * 8 + ((wm * 2 + mt) ^ (lane & 7));
                ah[mt] = ((const uint4*)(buf + A_HI))[i4];
                al[mt] = ((const uint4*)(buf + A_LO))[i4];
            }
            uint2 bh[3], bl[3];
            #pragma unroll
            for (int nt = 0; nt < 3; ++nt) {
                int i2 = (ks * 32 + lane) * 8 + ((wn * 3 + nt) ^ ((lane >> 1) & 7));
                bh[nt] = ((const uint2*)(buf + B_HI))[i2];
                bl[nt] = ((const uint2*)(buf + B_LO))[i2];
            }
            #pragma unroll
            for (int mt = 0; mt < 2; ++mt)
                #pragma unroll
                for (int nt = 0; nt < 3; ++nt) {
                    mma16(acc[mt][nt], ah[mt], bh[nt]);   // hi*hi
                    mma16(acc[mt][nt], ah[mt], bl[nt]);   // hi*lo
                    mma16(acc[mt][nt], al[mt], bh[nt]);   // lo*hi
                }
        }

        if (it + 1 < NITER)
            storeT((unsigned*)sm + ((it + 1) & 1) * BUF);
        __syncthreads();
    }

    // ---- epilogue: accums -> smem C [128][56] -> fused LSTM cell ----
    float* sC = sm;
    #pragma unroll
    for (int mt = 0; mt < 2; ++mt)
        #pragma unroll
        for (int nt = 0; nt < 3; ++nt) {
            int r0 = wm * 32 + mt * 16 + gq;
            int c0 = wn * 24 + nt * 8 + tg * 2;
            *(float2*)(sC + r0 * 56 + c0)       = make_float2(acc[mt][nt][0], acc[mt][nt][1]);
            *(float2*)(sC + (r0 + 8) * 56 + c0) = make_float2(acc[mt][nt][2], acc[mt][nt][3]);
        }
    __syncthreads();

    #pragma unroll
    for (int p = 0; p < 4; ++p) {
        int idx = tid + p * 256;           // 1024 (m,h) pairs per block
        int ml = idx >> 3, hl = idx & 7;
        const float* cp = sC + ml * 56 + hl * 6;
        const float* bp = sBias + hl * 6;

        float i_f = cp[0] + bp[0], g_f = cp[1] + bp[1], o_f = cp[2] + bp[2];
        float c_f = sigmoidf_(i_f) * tanhf(g_f);
        float h_f = sigmoidf_(o_f) * tanhf(c_f);
        float i_b = cp[3] + bp[3], g_b = cp[4] + bp[4], o_b = cp[5] + bp[5];
        float c_b = sigmoidf_(i_b) * tanhf(g_b);
        float h_b = sigmoidf_(o_b) * tanhf(c_b);

        int m = m0 + ml, h = h0 + hl;
        out[OUT_ENC + (size_t)(m * 2 + LAYER) * 512 + h] = h_f + h_b;
        if (LAYER == 0) {
            g_inp1[(size_t)m * 1024 + h]       = h_f;
            g_inp1[(size_t)m * 1024 + 512 + h] = h_b;
        }
        if ((m & 255) == 255) {
            int bb = m >> 8;
            out[LAYER * 16384 + bb * 512 + h]         = h_f;   // h_last
            out[OUT_C + LAYER * 16384 + bb * 512 + h] = c_f;   // c_last
        }
    }
}

extern "C" void kernel_launch(void* const* d_in, const int* in_sizes, int n_in,
                              void* d_out, int out_size)
{
    const int*   x    = (const int*)  d_in[0];
    const float* emb  = (const float*)d_in[1];
    const float* W0   = (const float*)d_in[2];   // (2, 2048, 512)
    const float* bih0 = (const float*)d_in[4];
    const float* bhh0 = (const float*)d_in[5];
    const float* W1   = (const float*)d_in[6];   // (2, 2048, 1024)
    const float* bih1 = (const float*)d_in[8];
    const float* bhh1 = (const float*)d_in[9];
    float* out = (float*)d_out;

    cudaFuncSetAttribute(lstm_bf16<0, 512>,
                         cudaFuncAttributeMaxDynamicSharedMemorySize, SMEM_BYTES);
    cudaFuncSetAttribute(lstm_bf16<1, 1024>,
                         cudaFuncAttributeMaxDynamicSharedMemorySize, SMEM_BYTES);

    dim3 grid(M_TOTAL / 128, 512 / 8);    // (64, 64)
    dim3 block(256);
    lstm_bf16<0, 512><<<grid, block, SMEM_BYTES>>>(x, emb, W0, bih0, bhh0, out);
    lstm_bf16<1, 1024><<<grid, block, SMEM_BYTES>>>(x, emb, W1, bih1, bhh1, out);
}